// round 7
// baseline (speedup 1.0000x reference)
#include <cuda_runtime.h>
#include <cstdint>

#define DIMC   256
#define NHEADS 8
#define HDIM   32
#define MAXN   10048

// Scratch (no cudaMalloc allowed).
__device__ float g_q[MAXN * DIMC];
__device__ float g_k[MAXN * DIMC];
__device__ float g_v[MAXN * DIMC];
__device__ float g_acc[MAXN * DIMC];

// Pre-split (3xTF32 hi/lo) operands, stored in the exact swizzled smem image:
// per row: 32 chunks x 4 float4 slots; slot index pre-XORed with (row&3).
// float4 = (hi[k0], hi[k1], lo[k0], lo[k1]) for k = chunk*8 + 2*slot + {0,1}.
__device__ float4 gx_s  [MAXN * 128];        // X split      (20.6 MB)
__device__ float4 gacc_s[MAXN * 128];        // g_acc split  (20.6 MB)
__device__ float4 gw_s  [4 * 256 * 128];     // Wq,Wk,Wv,Wo  ( 2.1 MB)

// ---------------------------------------------------------------------------
// tf32 helpers
// ---------------------------------------------------------------------------
__device__ __forceinline__ uint32_t f2tf32(float x) {
    uint32_t r;
    asm("cvt.rna.tf32.f32 %0, %1;" : "=r"(r) : "f"(x));
    return r;
}
__device__ __forceinline__ float4 mk_hilo(float x, float y) {
    uint32_t hx = f2tf32(x), hy = f2tf32(y);
    float lx = x - __uint_as_float(hx);
    float ly = y - __uint_as_float(hy);
    return make_float4(__uint_as_float(hx), __uint_as_float(hy),
                       __uint_as_float(f2tf32(lx)), __uint_as_float(f2tf32(ly)));
}
__device__ __forceinline__ void mma_tf32(float* c,
    uint32_t a0, uint32_t a1, uint32_t a2, uint32_t a3,
    uint32_t b0, uint32_t b1)
{
    asm volatile(
        "mma.sync.aligned.m16n8k8.row.col.f32.tf32.tf32.f32 "
        "{%0,%1,%2,%3}, {%4,%5,%6,%7}, {%8,%9}, {%0,%1,%2,%3};"
        : "+f"(c[0]), "+f"(c[1]), "+f"(c[2]), "+f"(c[3])
        : "r"(a0), "r"(a1), "r"(a2), "r"(a3), "r"(b0), "r"(b1));
}

// ---------------------------------------------------------------------------
// Zero the accumulator.
// ---------------------------------------------------------------------------
__global__ void __launch_bounds__(256) zero_acc_kernel(int n4) {
    int i = blockIdx.x * blockDim.x + threadIdx.x;
    float4 z = make_float4(0.f, 0.f, 0.f, 0.f);
    int stride = gridDim.x * blockDim.x;
    for (; i < n4; i += stride)
        reinterpret_cast<float4*>(g_acc)[i] = z;
}

// ---------------------------------------------------------------------------
// Split kernels: convert fp32 rows into the swizzled hi/lo image.
// One thread per (row, chunk): reads 8 floats, writes 4 float4 slots.
// NOTE: device-global destinations are referenced INSIDE device code only —
// passing a __device__ symbol as a host-side kernel argument is invalid.
// ---------------------------------------------------------------------------
__device__ __forceinline__ void split_rowchunk(
    const float* __restrict__ src, float4* __restrict__ dst, int r, int c)
{
    const float4* s = reinterpret_cast<const float4*>(src + (size_t)r * DIMC + c * 8);
    float4 x0 = s[0], x1 = s[1];
    float4* d = dst + ((size_t)r * 128 + c * 4);
    int sw = r & 3;
    d[0 ^ sw] = mk_hilo(x0.x, x0.y);
    d[1 ^ sw] = mk_hilo(x0.z, x0.w);
    d[2 ^ sw] = mk_hilo(x1.x, x1.y);
    d[3 ^ sw] = mk_hilo(x1.z, x1.w);
}

__global__ void __launch_bounds__(256) split_x_kernel(
    const float* __restrict__ src, int rows)
{
    int idx = blockIdx.x * blockDim.x + threadIdx.x;
    if (idx >= rows * 32) return;
    split_rowchunk(src, gx_s, idx >> 5, idx & 31);
}

__global__ void __launch_bounds__(256) split_acc_kernel(int rows)
{
    int idx = blockIdx.x * blockDim.x + threadIdx.x;
    if (idx >= rows * 32) return;
    split_rowchunk(g_acc, gacc_s, idx >> 5, idx & 31);
}

__global__ void __launch_bounds__(256) split_w_kernel(
    const float* __restrict__ Wq, const float* __restrict__ Wk,
    const float* __restrict__ Wv, const float* __restrict__ Wo)
{
    int idx = blockIdx.x * blockDim.x + threadIdx.x;   // 256*32 per matrix
    if (idx >= 256 * 32) return;
    const float* srcs[4] = {Wq, Wk, Wv, Wo};
    int z = blockIdx.y;
    split_rowchunk(srcs[z], gw_s + (size_t)z * 256 * 128, idx >> 5, idx & 31);
}

// ---------------------------------------------------------------------------
// 3xTF32 tensor-core GEMM on pre-split operands.
// CTA tile 128x64, 8 warps (warp tile 32x32), BK=16 (2 chunks/stage),
// double-buffered. Loader is a pure 64B-per-(row,chunk) copy.
// ---------------------------------------------------------------------------
#define BM 128
#define BN 64
#define NST16 (DIMC / 16)    // 16 stages

__device__ __forceinline__ void gemm_tf32s(
    const float4* __restrict__ Asrc, int M,
    const float4* __restrict__ Bsrc,
    const float* __restrict__ Bv,
    float* __restrict__ C,
    int m0, int n0)
{
    __shared__ float4 As[2][2][BM][4];   // 32 KB
    __shared__ float4 Bs[2][2][BN][4];   // 16 KB

    int tid  = threadIdx.x;
    int lane = tid & 31;
    int wid  = tid >> 5;
    int wm = (wid & 3) * 32;
    int wn = (wid >> 2) * 32;
    int gq = lane >> 2;
    int tq = lane & 3;

    // A loader: thread -> (row = tid>>1, ch = tid&1), copies 4 slots (64B).
    int arow = tid >> 1;
    int ach  = tid & 1;
    bool aval = (m0 + arow) < M;
    const float4* ap = Asrc + (size_t)(m0 + arow) * 128 + ach * 4;
    // B loader: thread -> 2 consecutive float4 (lin = 2*tid).
    int blin  = tid * 2;
    int brow  = blin >> 3;
    int bch   = (blin >> 2) & 1;
    int bslot = blin & 3;            // 0 or 2
    const float4* bp = Bsrc + (size_t)(n0 + brow) * 128 + bch * 4 + bslot;

    float acc[2][4][4];
#pragma unroll
    for (int mi = 0; mi < 2; mi++)
#pragma unroll
        for (int ni = 0; ni < 4; ni++)
#pragma unroll
            for (int j = 0; j < 4; j++) acc[mi][ni][j] = 0.f;

    const float4 zf4 = make_float4(0.f, 0.f, 0.f, 0.f);

    float4 ra[4], rb[2];
#pragma unroll
    for (int i = 0; i < 4; i++) ra[i] = aval ? ap[i] : zf4;
    rb[0] = bp[0]; rb[1] = bp[1];

    int buf = 0;
#pragma unroll
    for (int i = 0; i < 4; i++) As[0][ach][arow][i] = ra[i];
    Bs[0][bch][brow][bslot]     = rb[0];
    Bs[0][bch][brow][bslot + 1] = rb[1];
    __syncthreads();

#pragma unroll 1
    for (int st = 0; st < NST16; st++) {
        if (st + 1 < NST16) {
            const float4* apn = ap + (st + 1) * 8;
            const float4* bpn = bp + (st + 1) * 8;
#pragma unroll
            for (int i = 0; i < 4; i++) ra[i] = aval ? apn[i] : zf4;
            rb[0] = bpn[0]; rb[1] = bpn[1];
        }

#pragma unroll
        for (int ch = 0; ch < 2; ch++) {
            float4 af0[2], af1[2];
#pragma unroll
            for (int mi = 0; mi < 2; mi++) {
                int r0 = wm + mi * 16 + gq;
                af0[mi] = As[buf][ch][r0][tq ^ (r0 & 3)];
                af1[mi] = As[buf][ch][r0 + 8][tq ^ (r0 & 3)];
            }
            float4 bf[4];
#pragma unroll
            for (int ni = 0; ni < 4; ni++) {
                int rn = wn + ni * 8 + gq;
                bf[ni] = Bs[buf][ch][rn][tq ^ (rn & 3)];
            }
#pragma unroll
            for (int mi = 0; mi < 2; mi++) {
                uint32_t a0h = __float_as_uint(af0[mi].x);
                uint32_t a1h = __float_as_uint(af1[mi].x);
                uint32_t a2h = __float_as_uint(af0[mi].y);
                uint32_t a3h = __float_as_uint(af1[mi].y);
                uint32_t a0l = __float_as_uint(af0[mi].z);
                uint32_t a1l = __float_as_uint(af1[mi].z);
                uint32_t a2l = __float_as_uint(af0[mi].w);
                uint32_t a3l = __float_as_uint(af1[mi].w);
#pragma unroll
                for (int ni = 0; ni < 4; ni++) {
                    uint32_t b0h = __float_as_uint(bf[ni].x);
                    uint32_t b1h = __float_as_uint(bf[ni].y);
                    uint32_t b0l = __float_as_uint(bf[ni].z);
                    uint32_t b1l = __float_as_uint(bf[ni].w);
                    mma_tf32(acc[mi][ni], a0h, a1h, a2h, a3h, b0h, b1h);
                    mma_tf32(acc[mi][ni], a0h, a1h, a2h, a3h, b0l, b1l);
                    mma_tf32(acc[mi][ni], a0l, a1l, a2l, a3l, b0h, b1h);
                }
            }
        }

        if (st + 1 < NST16) {
            int nb = buf ^ 1;
#pragma unroll
            for (int i = 0; i < 4; i++) As[nb][ach][arow][i] = ra[i];
            Bs[nb][bch][brow][bslot]     = rb[0];
            Bs[nb][bch][brow][bslot + 1] = rb[1];
            __syncthreads();
            buf = nb;
        }
    }

    // ---- epilogue: bias + store ----
#pragma unroll
    for (int mi = 0; mi < 2; mi++) {
#pragma unroll
        for (int ni = 0; ni < 4; ni++) {
            int r0 = m0 + wm + mi * 16 + gq;
            int cc = n0 + wn + ni * 8 + 2 * tq;
            float2 bb = *reinterpret_cast<const float2*>(Bv + cc);
            if (r0 < M) {
                float2 o = make_float2(acc[mi][ni][0] + bb.x,
                                       acc[mi][ni][1] + bb.y);
                *reinterpret_cast<float2*>(C + (size_t)r0 * DIMC + cc) = o;
            }
            if (r0 + 8 < M) {
                float2 o = make_float2(acc[mi][ni][2] + bb.x,
                                       acc[mi][ni][3] + bb.y);
                *reinterpret_cast<float2*>(C + (size_t)(r0 + 8) * DIMC + cc) = o;
            }
        }
    }
}

__global__ void __launch_bounds__(256, 2) gemm_qkv_kernel(
    int M,
    const float* __restrict__ bq, const float* __restrict__ bk,
    const float* __restrict__ bv)
{
    int z = blockIdx.z;
    const float* B = (z == 0) ? bq : (z == 1) ? bk : bv;
    float* C = (z == 0) ? g_q : (z == 1) ? g_k : g_v;
    gemm_tf32s(gx_s, M, gw_s + (size_t)z * 256 * 128, B, C,
               blockIdx.y * BM, blockIdx.x * BN);
}

__global__ void __launch_bounds__(256, 2) gemm_out_kernel(
    int M, const float* __restrict__ bo, float* __restrict__ out)
{
    gemm_tf32s(gacc_s, M, gw_s + (size_t)3 * 256 * 128, bo, out,
               blockIdx.y * BM, blockIdx.x * BN);
}

// ---------------------------------------------------------------------------
// Edge kernel: one warp per edge.
// ---------------------------------------------------------------------------
__device__ __forceinline__ void red_add_v4(float* addr, float4 v) {
    asm volatile("red.global.add.v4.f32 [%0], {%1, %2, %3, %4};"
                 :: "l"(addr), "f"(v.x), "f"(v.y), "f"(v.z), "f"(v.w)
                 : "memory");
}

__global__ void __launch_bounds__(256) edge_kernel(
    const int* __restrict__ src, const int* __restrict__ dst, int E)
{
    int e = (blockIdx.x << 3) + (threadIdx.x >> 5);
    if (e >= E) return;
    int lane = threadIdx.x & 31;

    int s = src[e];
    int d = dst[e];

    const float4* qp = reinterpret_cast<const float4*>(g_q + (size_t)s * DIMC);
    const float4* kp = reinterpret_cast<const float4*>(g_k + (size_t)d * DIMC);

    float4 a0 = qp[lane];
    float4 a1 = qp[lane + 32];
    float4 b0 = kp[lane];
    float4 b1 = kp[lane + 32];

    float p0 = a0.x * b0.x + a0.y * b0.y + a0.z * b0.z + a0.w * b0.w;
    float p1 = a1.x * b1.x + a1.y * b1.y + a1.z * b1.z + a1.w * b1.w;

#pragma unroll
    for (int m = 1; m <= 4; m <<= 1) {
        p0 += __shfl_xor_sync(0xffffffffu, p0, m);
        p1 += __shfl_xor_sync(0xffffffffu, p1, m);
    }

    const float scale = 0.17677669529663687f;   // 1/sqrt(32)
    float sc0 = p0 * scale;
    float sc1 = p1 * scale;

    float sh[8];
#pragma unroll
    for (int h = 0; h < 4; h++) {
        sh[h]     = __shfl_sync(0xffffffffu, sc0, h << 3);
        sh[h + 4] = __shfl_sync(0xffffffffu, sc1, h << 3);
    }

    float mx = sh[0];
#pragma unroll
    for (int h = 1; h < 8; h++) mx = fmaxf(mx, sh[h]);
    float sum = 0.f;
#pragma unroll
    for (int h = 0; h < 8; h++) sum += expf(sh[h] - mx);
    float inv = 1.0f / sum;

    float w0 = expf(sc0 - mx) * inv;
    float w1 = expf(sc1 - mx) * inv;

    const float4* vp = reinterpret_cast<const float4*>(g_v + (size_t)s * DIMC);
    float4 v0 = vp[lane];
    float4 v1 = vp[lane + 32];

    float* op = g_acc + (size_t)d * DIMC;
    red_add_v4(op + (lane << 2),
               make_float4(v0.x * w0, v0.y * w0, v0.z * w0, v0.w * w0));
    red_add_v4(op + ((lane + 32) << 2),
               make_float4(v1.x * w1, v1.y * w1, v1.z * w1, v1.w * w1));
}

// ---------------------------------------------------------------------------
// Launch
// ---------------------------------------------------------------------------
extern "C" void kernel_launch(void* const* d_in, const int* in_sizes, int n_in,
                              void* d_out, int out_size)
{
    const float* x   = (const float*)d_in[0];
    const int*   src = (const int*)  d_in[1];
    const int*   dst = (const int*)  d_in[2];
    const float* Wq  = (const float*)d_in[3];
    const float* bq  = (const float*)d_in[4];
    const float* Wk  = (const float*)d_in[5];
    const float* bk  = (const float*)d_in[6];
    const float* Wv  = (const float*)d_in[7];
    const float* bv  = (const float*)d_in[8];
    const float* Wo  = (const float*)d_in[9];
    const float* bo  = (const float*)d_in[10];
    float* out = (float*)d_out;

    int N = in_sizes[0] / DIMC;
    int E = in_sizes[1];

    int mtiles = (N + BM - 1) / BM;
    int ntiles = DIMC / BN;

    // 1) zero accumulator + split inputs (device-global dst bound in device code)
    int n4 = (N * DIMC) / 4;
    zero_acc_kernel<<<(n4 + 255) / 256, 256>>>(n4);
    split_x_kernel<<<(N * 32 + 255) / 256, 256>>>(x, N);
    {
        dim3 grid((256 * 32 + 255) / 256, 4);
        split_w_kernel<<<grid, 256>>>(Wq, Wk, Wv, Wo);
    }

    // 2) Q/K/V projections (tensor cores, 3xTF32, pre-split)
    {
        dim3 grid(ntiles, mtiles, 3);
        gemm_qkv_kernel<<<grid, 256>>>(N, bq, bk, bv);
    }

    // 3) per-edge attention + scatter
    edge_kernel<<<(E + 7) / 8, 256>>>(src, dst, E);

    // 4) split the aggregated features, then output projection
    split_acc_kernel<<<(N * 32 + 255) / 256, 256>>>(N);
    {
        dim3 grid(ntiles, mtiles, 1);
        gemm_out_kernel<<<grid, 256>>>(N, bo, out);
    }
}

// round 8
// speedup vs baseline: 1.5771x; 1.5771x over previous
#include <cuda_runtime.h>
#include <cuda_bf16.h>
#include <cstdint>

#define DIMC   256
#define NHEADS 8
#define HDIM   32
#define MAXN   10240   // padded to cover the last 128-row tile (79*128+127 < 10240)

// Scratch (no cudaMalloc allowed).
__device__ float g_q[MAXN * DIMC];
__device__ float g_k[MAXN * DIMC];
__device__ float g_v[MAXN * DIMC];
__device__ float g_acc[MAXN * DIMC];

// Pre-split bf16 hi/lo operands in the swizzled smem image.
// Per row: 16 k16-chunks x 4 float4 slots (slot index pre-XORed with row&3).
// Slot s (s=0..3) float4 = (hiPair[s], hiPair[s+4], loPair[s], loPair[s+4]),
// where pair t = packed bf16x2 of k = (2t, 2t+1) within the chunk (u32 in float).
__device__ float4 gx_s  [MAXN * 64];        // X split      (10.5 MB)
__device__ float4 gacc_s[MAXN * 64];        // g_acc split  (10.5 MB)
__device__ float4 gw_s  [4 * 256 * 64];     // Wq,Wk,Wv,Wo  ( 1.0 MB)

// ---------------------------------------------------------------------------
// bf16 split helpers
// ---------------------------------------------------------------------------
__device__ __forceinline__ void split_pair(float a, float b,
                                           uint32_t& hp, uint32_t& lp)
{
    __nv_bfloat16 ha = __float2bfloat16(a);
    __nv_bfloat16 hb = __float2bfloat16(b);
    float la = a - __bfloat162float(ha);
    float lb = b - __bfloat162float(hb);
    __nv_bfloat16 la16 = __float2bfloat16(la);
    __nv_bfloat16 lb16 = __float2bfloat16(lb);
    hp = (uint32_t)__bfloat16_as_ushort(ha) | ((uint32_t)__bfloat16_as_ushort(hb) << 16);
    lp = (uint32_t)__bfloat16_as_ushort(la16) | ((uint32_t)__bfloat16_as_ushort(lb16) << 16);
}

__device__ __forceinline__ void mma_bf16(float* c,
    uint32_t a0, uint32_t a1, uint32_t a2, uint32_t a3,
    uint32_t b0, uint32_t b1)
{
    asm volatile(
        "mma.sync.aligned.m16n8k16.row.col.f32.bf16.bf16.f32 "
        "{%0,%1,%2,%3}, {%4,%5,%6,%7}, {%8,%9}, {%0,%1,%2,%3};"
        : "+f"(c[0]), "+f"(c[1]), "+f"(c[2]), "+f"(c[3])
        : "r"(a0), "r"(a1), "r"(a2), "r"(a3), "r"(b0), "r"(b1));
}

__device__ __forceinline__ void cpa16(uint32_t dst, const void* src) {
    asm volatile("cp.async.ca.shared.global [%0], [%1], 16;" :: "r"(dst), "l"(src));
}

// ---------------------------------------------------------------------------
// Zero the accumulator.
// ---------------------------------------------------------------------------
__global__ void __launch_bounds__(256) zero_acc_kernel(int n4) {
    int i = blockIdx.x * blockDim.x + threadIdx.x;
    float4 z = make_float4(0.f, 0.f, 0.f, 0.f);
    int stride = gridDim.x * blockDim.x;
    for (; i < n4; i += stride)
        reinterpret_cast<float4*>(g_acc)[i] = z;
}

// ---------------------------------------------------------------------------
// Split kernels. One thread per (row, k16 chunk): read 16 floats, write 4 f4.
// Device-global destinations are referenced only inside device code.
// ---------------------------------------------------------------------------
__device__ __forceinline__ void split_rowchunk(
    const float* __restrict__ src, float4* __restrict__ dst, int r, int c)
{
    const float4* s = reinterpret_cast<const float4*>(src + (size_t)r * DIMC + c * 16);
    float x[16];
    *reinterpret_cast<float4*>(x + 0)  = s[0];
    *reinterpret_cast<float4*>(x + 4)  = s[1];
    *reinterpret_cast<float4*>(x + 8)  = s[2];
    *reinterpret_cast<float4*>(x + 12) = s[3];
    uint32_t hp[8], lp[8];
#pragma unroll
    for (int t = 0; t < 8; t++) split_pair(x[2 * t], x[2 * t + 1], hp[t], lp[t]);
    float4* d = dst + ((size_t)r * 64 + c * 4);
    int sw = r & 3;
#pragma unroll
    for (int s2 = 0; s2 < 4; s2++)
        d[s2 ^ sw] = make_float4(__uint_as_float(hp[s2]), __uint_as_float(hp[s2 + 4]),
                                 __uint_as_float(lp[s2]), __uint_as_float(lp[s2 + 4]));
}

__global__ void __launch_bounds__(256) split_x_kernel(const float* __restrict__ src, int rows) {
    int idx = blockIdx.x * blockDim.x + threadIdx.x;
    if (idx >= rows * 16) return;
    split_rowchunk(src, gx_s, idx >> 4, idx & 15);
}

__global__ void __launch_bounds__(256) split_acc_kernel(int rows) {
    int idx = blockIdx.x * blockDim.x + threadIdx.x;
    if (idx >= rows * 16) return;
    split_rowchunk(g_acc, gacc_s, idx >> 4, idx & 15);
}

__global__ void __launch_bounds__(256) split_w_kernel(
    const float* __restrict__ Wq, const float* __restrict__ Wk,
    const float* __restrict__ Wv, const float* __restrict__ Wo)
{
    int idx = blockIdx.x * blockDim.x + threadIdx.x;   // 256*16 per matrix
    if (idx >= 256 * 16) return;
    const float* srcs[4] = {Wq, Wk, Wv, Wo};
    int z = blockIdx.y;
    split_rowchunk(srcs[z], gw_s + (size_t)z * 256 * 64, idx >> 4, idx & 15);
}

// ---------------------------------------------------------------------------
// 3xBF16 tensor-core GEMM (m16n8k16) on pre-split operands.
// CTA 128x64, 8 warps (warp tile 32x32), k16 chunks, 4-stage cp.async pipeline.
// ---------------------------------------------------------------------------
#define BM 128
#define BN 64
#define NCH 16        // k16 chunks over DIMC=256
#define STG 4

__device__ __forceinline__ void gemm_bf16s(
    const float4* __restrict__ Asrc, int M,
    const float4* __restrict__ Bsrc,
    const float* __restrict__ Bv,
    float* __restrict__ C,
    int m0, int n0)
{
    __shared__ float4 As[STG][BM][4];   // 32 KB
    __shared__ float4 Bs[STG][BN][4];   // 16 KB

    int tid  = threadIdx.x;
    int lane = tid & 31;
    int wid  = tid >> 5;
    int wm = (wid & 3) * 32;
    int wn = (wid >> 2) * 32;
    int gq = lane >> 2;
    int tq = lane & 3;

    // Loaders. A: thread -> (row=tid>>1, half=tid&1), 2 cp.async (32B).
    //          B: thread -> (row=tid>>2, slot=tid&3), 1 cp.async (16B).
    int arow = tid >> 1, ahalf = tid & 1;
    const float4* ap = Asrc + (size_t)(m0 + arow) * 64 + ahalf * 2;
    int brow = tid >> 2, bslot = tid & 3;
    const float4* bp = Bsrc + (size_t)(n0 + brow) * 64 + bslot;

    uint32_t sA = (uint32_t)__cvta_generic_to_shared(&As[0][0][0]);
    uint32_t sB = (uint32_t)__cvta_generic_to_shared(&Bs[0][0][0]);
    uint32_t daBase = sA + (uint32_t)((arow * 4 + ahalf * 2) * 16);
    uint32_t dbBase = sB + (uint32_t)((brow * 4 + bslot) * 16);

    float acc[2][4][4];
#pragma unroll
    for (int mi = 0; mi < 2; mi++)
#pragma unroll
        for (int ni = 0; ni < 4; ni++)
#pragma unroll
            for (int j = 0; j < 4; j++) acc[mi][ni][j] = 0.f;

    // Prologue: stages 0..2.
#pragma unroll
    for (int s = 0; s < STG - 1; s++) {
        uint32_t da = daBase + s * (BM * 64);
        uint32_t db = dbBase + s * (BN * 64);
        cpa16(da,      ap + s * 4);
        cpa16(da + 16, ap + s * 4 + 1);
        cpa16(db,      bp + s * 4);
        asm volatile("cp.async.commit_group;");
    }

#pragma unroll 1
    for (int ch = 0; ch < NCH; ch++) {
        asm volatile("cp.async.wait_group %0;" :: "n"(STG - 2) : "memory");
        __syncthreads();
        int st = ch & (STG - 1);

        float4 af0[2], af1[2], bfv[4];
#pragma unroll
        for (int mi = 0; mi < 2; mi++) {
            int r0 = wm + mi * 16 + gq;
            af0[mi] = As[st][r0][tq ^ (r0 & 3)];
            af1[mi] = As[st][r0 + 8][tq ^ (r0 & 3)];
        }
#pragma unroll
        for (int ni = 0; ni < 4; ni++) {
            int rn = wn + ni * 8 + gq;
            bfv[ni] = Bs[st][rn][tq ^ (rn & 3)];
        }

#pragma unroll
        for (int mi = 0; mi < 2; mi++) {
            uint32_t a0h = __float_as_uint(af0[mi].x);
            uint32_t a1h = __float_as_uint(af1[mi].x);
            uint32_t a2h = __float_as_uint(af0[mi].y);
            uint32_t a3h = __float_as_uint(af1[mi].y);
            uint32_t a0l = __float_as_uint(af0[mi].z);
            uint32_t a1l = __float_as_uint(af1[mi].z);
            uint32_t a2l = __float_as_uint(af0[mi].w);
            uint32_t a3l = __float_as_uint(af1[mi].w);
#pragma unroll
            for (int ni = 0; ni < 4; ni++) {
                uint32_t b0h = __float_as_uint(bfv[ni].x);
                uint32_t b1h = __float_as_uint(bfv[ni].y);
                uint32_t b0l = __float_as_uint(bfv[ni].z);
                uint32_t b1l = __float_as_uint(bfv[ni].w);
                mma_bf16(acc[mi][ni], a0h, a1h, a2h, a3h, b0h, b1h);
                mma_bf16(acc[mi][ni], a0h, a1h, a2h, a3h, b0l, b1l);
                mma_bf16(acc[mi][ni], a0l, a1l, a2l, a3l, b0h, b1h);
            }
        }

        // Issue stage ch+3 (overwrites the stage consumed in iter ch-1,
        // which all warps released at this iteration's __syncthreads).
        int nc = ch + STG - 1;
        if (nc < NCH) {
            int ns = nc & (STG - 1);
            uint32_t da = daBase + ns * (BM * 64);
            uint32_t db = dbBase + ns * (BN * 64);
            cpa16(da,      ap + nc * 4);
            cpa16(da + 16, ap + nc * 4 + 1);
            cpa16(db,      bp + nc * 4);
        }
        asm volatile("cp.async.commit_group;");
    }

    // ---- epilogue: bias + store ----
#pragma unroll
    for (int mi = 0; mi < 2; mi++) {
#pragma unroll
        for (int ni = 0; ni < 4; ni++) {
            int r0 = m0 + wm + mi * 16 + gq;
            int cc = n0 + wn + ni * 8 + 2 * tq;
            float2 bb = *reinterpret_cast<const float2*>(Bv + cc);
            if (r0 < M) {
                float2 o = make_float2(acc[mi][ni][0] + bb.x,
                                       acc[mi][ni][1] + bb.y);
                *reinterpret_cast<float2*>(C + (size_t)r0 * DIMC + cc) = o;
            }
            if (r0 + 8 < M) {
                float2 o = make_float2(acc[mi][ni][2] + bb.x,
                                       acc[mi][ni][3] + bb.y);
                *reinterpret_cast<float2*>(C + (size_t)(r0 + 8) * DIMC + cc) = o;
            }
        }
    }
}

__global__ void __launch_bounds__(256, 2) gemm_qkv_kernel(
    int M,
    const float* __restrict__ bq, const float* __restrict__ bk,
    const float* __restrict__ bv)
{
    int z = blockIdx.z;
    const float* B = (z == 0) ? bq : (z == 1) ? bk : bv;
    float* C = (z == 0) ? g_q : (z == 1) ? g_k : g_v;
    gemm_bf16s(gx_s, M, gw_s + (size_t)z * 256 * 64, B, C,
               blockIdx.y * BM, blockIdx.x * BN);
}

__global__ void __launch_bounds__(256, 2) gemm_out_kernel(
    int M, const float* __restrict__ bo, float* __restrict__ out)
{
    gemm_bf16s(gacc_s, M, gw_s + (size_t)3 * 256 * 64, bo, out,
               blockIdx.y * BM, blockIdx.x * BN);
}

// ---------------------------------------------------------------------------
// Edge kernel: one warp per edge.
// ---------------------------------------------------------------------------
__device__ __forceinline__ void red_add_v4(float* addr, float4 v) {
    asm volatile("red.global.add.v4.f32 [%0], {%1, %2, %3, %4};"
                 :: "l"(addr), "f"(v.x), "f"(v.y), "f"(v.z), "f"(v.w)
                 : "memory");
}

__global__ void __launch_bounds__(256) edge_kernel(
    const int* __restrict__ src, const int* __restrict__ dst, int E)
{
    int e = (blockIdx.x << 3) + (threadIdx.x >> 5);
    if (e >= E) return;
    int lane = threadIdx.x & 31;

    int s = src[e];
    int d = dst[e];

    const float4* qp = reinterpret_cast<const float4*>(g_q + (size_t)s * DIMC);
    const float4* kp = reinterpret_cast<const float4*>(g_k + (size_t)d * DIMC);

    float4 a0 = qp[lane];
    float4 a1 = qp[lane + 32];
    float4 b0 = kp[lane];
    float4 b1 = kp[lane + 32];

    float p0 = a0.x * b0.x + a0.y * b0.y + a0.z * b0.z + a0.w * b0.w;
    float p1 = a1.x * b1.x + a1.y * b1.y + a1.z * b1.z + a1.w * b1.w;

#pragma unroll
    for (int m = 1; m <= 4; m <<= 1) {
        p0 += __shfl_xor_sync(0xffffffffu, p0, m);
        p1 += __shfl_xor_sync(0xffffffffu, p1, m);
    }

    const float scale = 0.17677669529663687f;   // 1/sqrt(32)
    float sc0 = p0 * scale;
    float sc1 = p1 * scale;

    float sh[8];
#pragma unroll
    for (int h = 0; h < 4; h++) {
        sh[h]     = __shfl_sync(0xffffffffu, sc0, h << 3);
        sh[h + 4] = __shfl_sync(0xffffffffu, sc1, h << 3);
    }

    float mx = sh[0];
#pragma unroll
    for (int h = 1; h < 8; h++) mx = fmaxf(mx, sh[h]);
    float sum = 0.f;
#pragma unroll
    for (int h = 0; h < 8; h++) sum += expf(sh[h] - mx);
    float inv = 1.0f / sum;

    float w0 = expf(sc0 - mx) * inv;
    float w1 = expf(sc1 - mx) * inv;

    const float4* vp = reinterpret_cast<const float4*>(g_v + (size_t)s * DIMC);
    float4 v0 = vp[lane];
    float4 v1 = vp[lane + 32];

    float* op = g_acc + (size_t)d * DIMC;
    red_add_v4(op + (lane << 2),
               make_float4(v0.x * w0, v0.y * w0, v0.z * w0, v0.w * w0));
    red_add_v4(op + ((lane + 32) << 2),
               make_float4(v1.x * w1, v1.y * w1, v1.z * w1, v1.w * w1));
}

// ---------------------------------------------------------------------------
// Launch
// ---------------------------------------------------------------------------
extern "C" void kernel_launch(void* const* d_in, const int* in_sizes, int n_in,
                              void* d_out, int out_size)
{
    const float* x   = (const float*)d_in[0];
    const int*   src = (const int*)  d_in[1];
    const int*   dst = (const int*)  d_in[2];
    const float* Wq  = (const float*)d_in[3];
    const float* bq  = (const float*)d_in[4];
    const float* Wk  = (const float*)d_in[5];
    const float* bk  = (const float*)d_in[6];
    const float* Wv  = (const float*)d_in[7];
    const float* bv  = (const float*)d_in[8];
    const float* Wo  = (const float*)d_in[9];
    const float* bo  = (const float*)d_in[10];
    float* out = (float*)d_out;

    int N = in_sizes[0] / DIMC;
    int E = in_sizes[1];

    int mtiles = (N + BM - 1) / BM;
    int ntiles = DIMC / BN;

    // 1) zero accumulator + split inputs
    int n4 = (N * DIMC) / 4;
    zero_acc_kernel<<<(n4 + 255) / 256, 256>>>(n4);
    split_x_kernel<<<(N * 16 + 255) / 256, 256>>>(x, N);
    {
        dim3 grid((256 * 16 + 255) / 256, 4);
        split_w_kernel<<<grid, 256>>>(Wq, Wk, Wv, Wo);
    }

    // 2) Q/K/V projections (bf16 3-term split, m16n8k16)
    {
        dim3 grid(ntiles, mtiles, 3);
        gemm_qkv_kernel<<<grid, 256>>>(N, bq, bk, bv);
    }

    // 3) per-edge attention + scatter
    edge_kernel<<<(E + 7) / 8, 256>>>(src, dst, E);

    // 4) split aggregated features, output projection
    split_acc_kernel<<<(N * 16 + 255) / 256, 256>>>(N);
    {
        dim3 grid(ntiles, mtiles, 1);
        gemm_out_kernel<<<grid, 256>>>(N, bo, out);
    }
}